// round 5
// baseline (speedup 1.0000x reference)
#include <cuda_runtime.h>
#include <cuda_fp16.h>
#include <math.h>
#include <stdint.h>

// Problem constants
#define BATCH 256
#define DIM   1024
#define L_IM  37
#define L_S   33
#define LI    36
#define LS    30
#define MARGIN 0.2f

#define MROWS  (BATCH*LI)     // 9216
#define NCOLS  (BATCH*LS)     // 7680

// ---- device scratch (allocation-free rule) ----
__device__ __half g_A[(size_t)MROWS * DIM];          // fp16 normalized images   18.9 MB
__device__ __half g_B[(size_t)NCOLS * DIM];          // fp16 normalized words    15.7 MB
__device__ float  g_colmax[(size_t)BATCH * NCOLS];   // masked max over regions  7.9 MB
__device__ float  g_scores[BATCH * BATCH];
__device__ float  g_red[BATCH];

__device__ __forceinline__ uint32_t s2u(const void* p) {
    return (uint32_t)__cvta_generic_to_shared(p);
}

// ============================================================================
// Kernel 1: L2-normalize + slice + fp16 convert. One block per output row.
// ============================================================================
__global__ void norm_kernel(const float* __restrict__ in, int Lin, int Lout, int which)
{
    int ob = blockIdx.x;
    int b  = ob / Lout;
    int i  = ob % Lout;
    const float4* src = (const float4*)(in + ((size_t)b * Lin + i + 1) * DIM);
    float4 v = src[threadIdx.x];

    float ss = v.x*v.x + v.y*v.y + v.z*v.z + v.w*v.w;
    #pragma unroll
    for (int o = 16; o > 0; o >>= 1) ss += __shfl_down_sync(0xffffffffu, ss, o);

    __shared__ float warp_s[8];
    __shared__ float inv_s;
    if ((threadIdx.x & 31) == 0) warp_s[threadIdx.x >> 5] = ss;
    __syncthreads();
    if (threadIdx.x == 0) {
        float tot = 0.f;
        #pragma unroll
        for (int q = 0; q < 8; q++) tot += warp_s[q];
        inv_s = 1.0f / fmaxf(sqrtf(tot), 1e-12f);
    }
    __syncthreads();
    float inv = inv_s;

    __half2 h01 = __floats2half2_rn(v.x * inv, v.y * inv);
    __half2 h23 = __floats2half2_rn(v.z * inv, v.w * inv);
    __half* dst = (which ? g_B : g_A) + (size_t)ob * DIM + 4 * threadIdx.x;
    *(__half2*)(dst)     = h01;
    *(__half2*)(dst + 2) = h23;
}

// ============================================================================
// Kernel 2: fp16 mma.sync GEMM with FUSED masked max-over-regions epilogue.
//   CTA 144x256x32 (144 rows = exactly 4 images), 384 threads,
//   12 warps of 48x64 (3 m-groups x 4 n-groups), 4-stage cp.async pipeline.
//   B fragments via ldmatrix.x4 (layout matches non-trans distribution).
// ============================================================================
#define BM 144
#define BN 256
#define BKH 32                      // K halfs per stage
#define STAGES 4
#define ROWB 80                     // padded smem row bytes (32 halfs + 8 pad)
#define STAGE_BYTES ((BM + BN) * ROWB)   // 32000
#define KTILES (DIM / BKH)          // 32
#define NTH 384
#define ESTR 260                    // epilogue fp32 tile row stride (floats)
#define SMEM_TOTAL (BM * ESTR * 4 > STAGES * STAGE_BYTES ? BM * ESTR * 4 : STAGES * STAGE_BYTES)

__device__ __forceinline__ void cp16(uint32_t dst, const void* src) {
    asm volatile("cp.async.cg.shared.global [%0], [%1], 16;" :: "r"(dst), "l"(src));
}

__device__ __forceinline__ void load_stage(char* dsm, int slot, int m0, int n0, int kc, int t)
{
    char* As = dsm + slot * STAGE_BYTES;
    char* Bs = As + BM * ROWB;
    const __half* Agp = g_A + (size_t)m0 * DIM + kc * BKH;
    const __half* Bgp = g_B + (size_t)n0 * DIM + kc * BKH;
    #pragma unroll
    for (int i = 0; i < 2; i++) {                 // 576 A-vectors
        int idx = t + i * NTH;
        if (idx < 576) {
            int row = idx >> 2, seg = idx & 3;
            cp16(s2u(As + row * ROWB + seg * 16), Agp + (size_t)row * DIM + seg * 8);
        }
    }
    #pragma unroll
    for (int i = 0; i < 3; i++) {                 // 1024 B-vectors
        int idx = t + i * NTH;
        if (idx < 1024) {
            int row = idx >> 2, seg = idx & 3;
            cp16(s2u(Bs + row * ROWB + seg * 16), Bgp + (size_t)row * DIM + seg * 8);
        }
    }
}

__global__ __launch_bounds__(NTH, 1) void gemm_kernel(const int* __restrict__ im_len)
{
    extern __shared__ __align__(128) char dsm[];
    const int t   = threadIdx.x;
    const int wid = t >> 5, lid = t & 31;
    const int warp_m = (wid % 3) * 48;
    const int warp_n = (wid / 3) * 64;
    const int m0 = blockIdx.y * BM;
    const int n0 = blockIdx.x * BN;

    float acc[3][8][4];
    #pragma unroll
    for (int mf = 0; mf < 3; mf++)
        #pragma unroll
        for (int nf = 0; nf < 8; nf++)
            #pragma unroll
            for (int q = 0; q < 4; q++) acc[mf][nf][q] = 0.f;

    #pragma unroll
    for (int s = 0; s < STAGES - 1; s++) {
        load_stage(dsm, s, m0, n0, s, t);
        asm volatile("cp.async.commit_group;");
    }

    // B ldmatrix lane address offsets (within Bs, per warp):
    //   grp = lid>>3 selects matrix: {n0-7,k0-7},{n0-7,k8-15},{n8-15,k0-7},{n8-15,k8-15}
    const int bgrp = lid >> 3, brow = lid & 7;
    const int b_nrow  = (bgrp >> 1) * 8 + brow;       // n row within 16-block
    const int b_koff  = (bgrp & 1) * 16;              // byte offset for k-half

    for (int j = 0; j < KTILES; j++) {
        if (j < KTILES - 2)       asm volatile("cp.async.wait_group 2;");
        else if (j == KTILES - 2) asm volatile("cp.async.wait_group 1;");
        else                      asm volatile("cp.async.wait_group 0;");
        __syncthreads();

        int jl = j + STAGES - 1;
        if (jl < KTILES) {
            load_stage(dsm, jl & 3, m0, n0, jl, t);
            asm volatile("cp.async.commit_group;");
        }

        char* As = dsm + (j & 3) * STAGE_BYTES;
        const uint32_t AsU = s2u(As);
        const uint32_t BsU = AsU + BM * ROWB;

        #pragma unroll
        for (int ks = 0; ks < 2; ks++) {
            uint32_t a[3][4];
            #pragma unroll
            for (int mf = 0; mf < 3; mf++) {
                uint32_t addr = AsU + (warp_m + mf * 16 + (lid & 15)) * ROWB
                                    + ((lid >> 4) * 8 + ks * 16) * 2;
                asm volatile("ldmatrix.sync.aligned.m8n8.x4.shared.b16 {%0,%1,%2,%3}, [%4];"
                    : "=r"(a[mf][0]), "=r"(a[mf][1]), "=r"(a[mf][2]), "=r"(a[mf][3])
                    : "r"(addr));
            }
            uint32_t bf[4][4];        // [nf-pair][4 regs: nf-even b0,b1, nf-odd b0,b1]
            #pragma unroll
            for (int np = 0; np < 4; np++) {
                uint32_t addr = BsU + (warp_n + np * 16 + b_nrow) * ROWB
                                    + ks * 32 + b_koff;
                asm volatile("ldmatrix.sync.aligned.m8n8.x4.shared.b16 {%0,%1,%2,%3}, [%4];"
                    : "=r"(bf[np][0]), "=r"(bf[np][1]), "=r"(bf[np][2]), "=r"(bf[np][3])
                    : "r"(addr));
            }
            #pragma unroll
            for (int nf = 0; nf < 8; nf++) {
                uint32_t b0 = bf[nf >> 1][(nf & 1) * 2];
                uint32_t b1 = bf[nf >> 1][(nf & 1) * 2 + 1];
                #pragma unroll
                for (int mf = 0; mf < 3; mf++) {
                    asm volatile(
                        "mma.sync.aligned.m16n8k16.row.col.f32.f16.f16.f32 "
                        "{%0,%1,%2,%3}, {%4,%5,%6,%7}, {%8,%9}, {%0,%1,%2,%3};"
                        : "+f"(acc[mf][nf][0]), "+f"(acc[mf][nf][1]),
                          "+f"(acc[mf][nf][2]), "+f"(acc[mf][nf][3])
                        : "r"(a[mf][0]), "r"(a[mf][1]), "r"(a[mf][2]), "r"(a[mf][3]),
                          "r"(b0), "r"(b1));
                }
            }
        }
    }

    // ---- fused epilogue: accs -> smem fp32 tile [144][256] (stride ESTR) ----
    __syncthreads();
    float* etile = (float*)dsm;            // 144*260*4 = 149760 B
    const int r0 = warp_m + (lid >> 2);
    const int c0 = warp_n + (lid & 3) * 2;
    #pragma unroll
    for (int mf = 0; mf < 3; mf++) {
        #pragma unroll
        for (int nf = 0; nf < 8; nf++) {
            int r = r0 + mf * 16;
            int c = c0 + nf * 8;
            etile[r * ESTR + c]           = acc[mf][nf][0];
            etile[r * ESTR + c + 1]       = acc[mf][nf][1];
            etile[(r + 8) * ESTR + c]     = acc[mf][nf][2];
            etile[(r + 8) * ESTR + c + 1] = acc[mf][nf][3];
        }
    }
    __syncthreads();

    // masked column max per (image, col): 4 images x 256 cols = 1024 outputs
    const int bimg0 = blockIdx.y * 4;
    for (int idx = t; idx < 4 * BN; idx += NTH) {
        int img = idx >> 8, col = idx & 255;
        int iml = im_len[bimg0 + img] - 1;           // valid rows (9..36)
        const float* colp = etile + img * 36 * ESTR + col;
        float m = -1e30f;
        for (int r = 0; r < iml; r++) m = fmaxf(m, colp[r * ESTR]);
        if (iml < LI) m = fmaxf(m, 0.f);             // reference zeros padded rows
        g_colmax[(size_t)(bimg0 + img) * NCOLS + n0 + col] = m;
    }
}

// ============================================================================
// Kernel 3: scores[b][c] = sum_{j < sl} colmax[b][c*30+j]. One warp per (b,c).
// ============================================================================
__global__ void score_kernel(const int* __restrict__ s_len)
{
    int wid = threadIdx.x >> 5, lid = threadIdx.x & 31;
    int p = blockIdx.x * 8 + wid;
    int b = p >> 8, c = p & 255;
    int sl = s_len[c] - 3;
    if (sl > LS) sl = LS;
    if (sl < 0)  sl = 0;
    float v = 0.f;
    if (lid < sl) v = g_colmax[(size_t)b * NCOLS + c * LS + lid];
    #pragma unroll
    for (int o = 16; o > 0; o >>= 1) v += __shfl_down_sync(0xffffffffu, v, o);
    if (lid == 0) g_scores[b * BATCH + c] = v;
}

// ============================================================================
// Kernel 4/5: contrastive loss
// ============================================================================
__global__ void loss1_kernel()
{
    int b = blockIdx.x, t = threadIdx.x;
    __shared__ float sd;
    __shared__ float w1[8], w2[8];
    if (t == 0) sd = g_scores[b * BATCH + b];
    __syncthreads();
    float d = sd;
    float v1 = 0.f, v2 = 0.f;
    if (t != b) {
        v1 = fmaxf(0.f, MARGIN + g_scores[b * BATCH + t] - d);
        v2 = fmaxf(0.f, MARGIN + g_scores[t * BATCH + b] - d);
    }
    #pragma unroll
    for (int o = 16; o > 0; o >>= 1) {
        v1 = fmaxf(v1, __shfl_down_sync(0xffffffffu, v1, o));
        v2 = fmaxf(v2, __shfl_down_sync(0xffffffffu, v2, o));
    }
    if ((t & 31) == 0) { w1[t >> 5] = v1; w2[t >> 5] = v2; }
    __syncthreads();
    if (t == 0) {
        float m1 = w1[0], m2 = w2[0];
        #pragma unroll
        for (int q = 1; q < 8; q++) { m1 = fmaxf(m1, w1[q]); m2 = fmaxf(m2, w2[q]); }
        g_red[b] = m1 + m2;
    }
}
__global__ void loss2_kernel(float* __restrict__ out)
{
    __shared__ float sm[BATCH];
    int t = threadIdx.x;
    sm[t] = g_red[t];
    __syncthreads();
    #pragma unroll
    for (int o = 128; o > 0; o >>= 1) {
        if (t < o) sm[t] += sm[t + o];
        __syncthreads();
    }
    if (t == 0) out[0] = sm[0];
}

// ============================================================================
extern "C" void kernel_launch(void* const* d_in, const int* in_sizes, int n_in,
                              void* d_out, int out_size)
{
    const float* im_set = (const float*)d_in[0];
    const float* s_seq  = (const float*)d_in[1];
    const int*   im_len = (const int*)d_in[2];
    const int*   s_len  = (const int*)d_in[3];
    float* out = (float*)d_out;

    cudaFuncSetAttribute(gemm_kernel, cudaFuncAttributeMaxDynamicSharedMemorySize,
                         SMEM_TOTAL);

    norm_kernel<<<BATCH * LI, 256>>>(im_set, L_IM, LI, 0);
    norm_kernel<<<BATCH * LS, 256>>>(s_seq,  L_S,  LS, 1);

    dim3 grid(NCOLS / BN, MROWS / BM);   // (30, 64)
    gemm_kernel<<<grid, NTH, SMEM_TOTAL>>>(im_len);

    score_kernel<<<BATCH * BATCH / 8, 256>>>(s_len);

    loss1_kernel<<<BATCH, 256>>>();
    loss2_kernel<<<1, BATCH>>>(out);
}

// round 6
// speedup vs baseline: 1.1203x; 1.1203x over previous
#include <cuda_runtime.h>
#include <cuda_fp16.h>
#include <math.h>
#include <stdint.h>

// Problem constants
#define BATCH 256
#define DIM   1024
#define L_IM  37
#define L_S   33
#define LI    36
#define LS    30
#define MARGIN 0.2f

#define MROWS  (BATCH*LI)     // 9216
#define NCOLS  (BATCH*LS)     // 7680

// ---- device scratch (allocation-free rule) ----
__device__ __half g_A[(size_t)MROWS * DIM];          // fp16 normalized images   18.9 MB
__device__ __half g_B[(size_t)NCOLS * DIM];          // fp16 normalized words    15.7 MB
__device__ float  g_colmax[(size_t)BATCH * NCOLS];   // masked max over regions  7.9 MB
__device__ float  g_scores[BATCH * BATCH];
__device__ float  g_red[BATCH];

__device__ __forceinline__ uint32_t s2u(const void* p) {
    return (uint32_t)__cvta_generic_to_shared(p);
}

// ============================================================================
// Kernel 1: L2-normalize + slice + fp16 convert. One block per output row.
// ============================================================================
__global__ void norm_kernel(const float* __restrict__ in, int Lin, int Lout, int which)
{
    int ob = blockIdx.x;
    int b  = ob / Lout;
    int i  = ob % Lout;
    const float4* src = (const float4*)(in + ((size_t)b * Lin + i + 1) * DIM);
    float4 v = src[threadIdx.x];

    float ss = v.x*v.x + v.y*v.y + v.z*v.z + v.w*v.w;
    #pragma unroll
    for (int o = 16; o > 0; o >>= 1) ss += __shfl_down_sync(0xffffffffu, ss, o);

    __shared__ float warp_s[8];
    __shared__ float inv_s;
    if ((threadIdx.x & 31) == 0) warp_s[threadIdx.x >> 5] = ss;
    __syncthreads();
    if (threadIdx.x == 0) {
        float tot = 0.f;
        #pragma unroll
        for (int q = 0; q < 8; q++) tot += warp_s[q];
        inv_s = 1.0f / fmaxf(sqrtf(tot), 1e-12f);
    }
    __syncthreads();
    float inv = inv_s;

    __half2 h01 = __floats2half2_rn(v.x * inv, v.y * inv);
    __half2 h23 = __floats2half2_rn(v.z * inv, v.w * inv);
    __half* dst = (which ? g_B : g_A) + (size_t)ob * DIM + 4 * threadIdx.x;
    *(__half2*)(dst)     = h01;
    *(__half2*)(dst + 2) = h23;
}

// ============================================================================
// Kernel 2: fp16 mma.sync GEMM with FUSED masked max-over-regions epilogue.
//   CTA 144x128x32 (144 rows = exactly 4 images), 192 threads, occ 2,
//   6 warps of 48x64 (3 m-groups x 2 n-groups), 4-stage cp.async pipeline.
//   A and B fragments both via ldmatrix.x4.
// ============================================================================
#define BM 144
#define BN 128
#define BKH 32                      // K halfs per stage
#define STAGES 4
#define ROWB 80                     // padded smem row bytes (32 halfs + 8 pad)
#define STAGE_BYTES ((BM + BN) * ROWB)   // 21760
#define KTILES (DIM / BKH)          // 32
#define NTH 192
#define ESTR 132                    // epilogue fp32 tile row stride (floats)

__device__ __forceinline__ void cp16(uint32_t dst, const void* src) {
    asm volatile("cp.async.cg.shared.global [%0], [%1], 16;" :: "r"(dst), "l"(src));
}

__device__ __forceinline__ void load_stage(char* dsm, int slot, int m0, int n0, int kc, int t)
{
    char* As = dsm + slot * STAGE_BYTES;
    char* Bs = As + BM * ROWB;
    const __half* Agp = g_A + (size_t)m0 * DIM + kc * BKH;
    const __half* Bgp = g_B + (size_t)n0 * DIM + kc * BKH;
    #pragma unroll
    for (int i = 0; i < 3; i++) {                 // 576 = 3 * 192 A-vectors
        int idx = t + i * NTH;
        int row = idx >> 2, seg = idx & 3;
        cp16(s2u(As + row * ROWB + seg * 16), Agp + (size_t)row * DIM + seg * 8);
    }
    #pragma unroll
    for (int i = 0; i < 3; i++) {                 // 512 B-vectors (last iter partial)
        int idx = t + i * NTH;
        if (idx < 512) {
            int row = idx >> 2, seg = idx & 3;
            cp16(s2u(Bs + row * ROWB + seg * 16), Bgp + (size_t)row * DIM + seg * 8);
        }
    }
}

__global__ __launch_bounds__(NTH, 2) void gemm_kernel(const int* __restrict__ im_len)
{
    extern __shared__ __align__(128) char dsm[];
    const int t   = threadIdx.x;
    const int wid = t >> 5, lid = t & 31;
    const int warp_m = (wid % 3) * 48;
    const int warp_n = (wid / 3) * 64;
    const int m0 = blockIdx.y * BM;
    const int n0 = blockIdx.x * BN;

    float acc[3][8][4];
    #pragma unroll
    for (int mf = 0; mf < 3; mf++)
        #pragma unroll
        for (int nf = 0; nf < 8; nf++)
            #pragma unroll
            for (int q = 0; q < 4; q++) acc[mf][nf][q] = 0.f;

    #pragma unroll
    for (int s = 0; s < STAGES - 1; s++) {
        load_stage(dsm, s, m0, n0, s, t);
        asm volatile("cp.async.commit_group;");
    }

    // B ldmatrix lane address components (validated in R5):
    //   grp = lid>>3 selects matrix {n-half, k-half}; row = lid&7
    const int b_nrow = ((lid >> 4) & 1) * 8 + (lid & 7);   // n row within 16-block
    const int b_koff = ((lid >> 3) & 1) * 16;              // byte offset for k-half

    for (int j = 0; j < KTILES; j++) {
        if (j < KTILES - 2)       asm volatile("cp.async.wait_group 2;");
        else if (j == KTILES - 2) asm volatile("cp.async.wait_group 1;");
        else                      asm volatile("cp.async.wait_group 0;");
        __syncthreads();

        int jl = j + STAGES - 1;
        if (jl < KTILES) {
            load_stage(dsm, jl & 3, m0, n0, jl, t);
            asm volatile("cp.async.commit_group;");
        }

        char* As = dsm + (j & 3) * STAGE_BYTES;
        const uint32_t AsU = s2u(As);
        const uint32_t BsU = AsU + BM * ROWB;

        #pragma unroll
        for (int ks = 0; ks < 2; ks++) {
            uint32_t a[3][4];
            #pragma unroll
            for (int mf = 0; mf < 3; mf++) {
                uint32_t addr = AsU + (warp_m + mf * 16 + (lid & 15)) * ROWB
                                    + ((lid >> 4) * 8 + ks * 16) * 2;
                asm volatile("ldmatrix.sync.aligned.m8n8.x4.shared.b16 {%0,%1,%2,%3}, [%4];"
                    : "=r"(a[mf][0]), "=r"(a[mf][1]), "=r"(a[mf][2]), "=r"(a[mf][3])
                    : "r"(addr));
            }
            uint32_t bf[4][4];        // [np: 16-n block][regs: nf-even b0,b1, nf-odd b0,b1]
            #pragma unroll
            for (int np = 0; np < 4; np++) {
                uint32_t addr = BsU + (warp_n + np * 16 + b_nrow) * ROWB
                                    + ks * 32 + b_koff;
                asm volatile("ldmatrix.sync.aligned.m8n8.x4.shared.b16 {%0,%1,%2,%3}, [%4];"
                    : "=r"(bf[np][0]), "=r"(bf[np][1]), "=r"(bf[np][2]), "=r"(bf[np][3])
                    : "r"(addr));
            }
            #pragma unroll
            for (int nf = 0; nf < 8; nf++) {
                uint32_t b0 = bf[nf >> 1][(nf & 1) * 2];
                uint32_t b1 = bf[nf >> 1][(nf & 1) * 2 + 1];
                #pragma unroll
                for (int mf = 0; mf < 3; mf++) {
                    asm volatile(
                        "mma.sync.aligned.m16n8k16.row.col.f32.f16.f16.f32 "
                        "{%0,%1,%2,%3}, {%4,%5,%6,%7}, {%8,%9}, {%0,%1,%2,%3};"
                        : "+f"(acc[mf][nf][0]), "+f"(acc[mf][nf][1]),
                          "+f"(acc[mf][nf][2]), "+f"(acc[mf][nf][3])
                        : "r"(a[mf][0]), "r"(a[mf][1]), "r"(a[mf][2]), "r"(a[mf][3]),
                          "r"(b0), "r"(b1));
                }
            }
        }
    }

    // ---- fused epilogue: accs -> smem fp32 tile [144][128] (stride ESTR) ----
    __syncthreads();
    float* etile = (float*)dsm;            // 144*132*4 = 76032 B
    const int r0 = warp_m + (lid >> 2);
    const int c0 = warp_n + (lid & 3) * 2;
    #pragma unroll
    for (int mf = 0; mf < 3; mf++) {
        #pragma unroll
        for (int nf = 0; nf < 8; nf++) {
            int r = r0 + mf * 16;
            int c = c0 + nf * 8;
            etile[r * ESTR + c]           = acc[mf][nf][0];
            etile[r * ESTR + c + 1]       = acc[mf][nf][1];
            etile[(r + 8) * ESTR + c]     = acc[mf][nf][2];
            etile[(r + 8) * ESTR + c + 1] = acc[mf][nf][3];
        }
    }
    __syncthreads();

    // masked column max per (image, col): 4 images x 128 cols = 512 outputs
    const int bimg0 = blockIdx.y * 4;
    for (int idx = t; idx < 512; idx += NTH) {
        int img = idx >> 7, col = idx & 127;
        int iml = im_len[bimg0 + img] - 1;           // valid rows (9..36)
        const float* colp = etile + img * 36 * ESTR + col;
        float m = -1e30f;
        for (int r = 0; r < iml; r++) m = fmaxf(m, colp[r * ESTR]);
        if (iml < LI) m = fmaxf(m, 0.f);             // reference zeros padded rows
        g_colmax[(size_t)(bimg0 + img) * NCOLS + n0 + col] = m;
    }
}

// ============================================================================
// Kernel 3: scores[b][c] = sum_{j < sl} colmax[b][c*30+j]. One warp per (b,c).
// ============================================================================
__global__ void score_kernel(const int* __restrict__ s_len)
{
    int wid = threadIdx.x >> 5, lid = threadIdx.x & 31;
    int p = blockIdx.x * 8 + wid;
    int b = p >> 8, c = p & 255;
    int sl = s_len[c] - 3;
    if (sl > LS) sl = LS;
    if (sl < 0)  sl = 0;
    float v = 0.f;
    if (lid < sl) v = g_colmax[(size_t)b * NCOLS + c * LS + lid];
    #pragma unroll
    for (int o = 16; o > 0; o >>= 1) v += __shfl_down_sync(0xffffffffu, v, o);
    if (lid == 0) g_scores[b * BATCH + c] = v;
}

// ============================================================================
// Kernel 4/5: contrastive loss
// ============================================================================
__global__ void loss1_kernel()
{
    int b = blockIdx.x, t = threadIdx.x;
    __shared__ float sd;
    __shared__ float w1[8], w2[8];
    if (t == 0) sd = g_scores[b * BATCH + b];
    __syncthreads();
    float d = sd;
    float v1 = 0.f, v2 = 0.f;
    if (t != b) {
        v1 = fmaxf(0.f, MARGIN + g_scores[b * BATCH + t] - d);
        v2 = fmaxf(0.f, MARGIN + g_scores[t * BATCH + b] - d);
    }
    #pragma unroll
    for (int o = 16; o > 0; o >>= 1) {
        v1 = fmaxf(v1, __shfl_down_sync(0xffffffffu, v1, o));
        v2 = fmaxf(v2, __shfl_down_sync(0xffffffffu, v2, o));
    }
    if ((t & 31) == 0) { w1[t >> 5] = v1; w2[t >> 5] = v2; }
    __syncthreads();
    if (t == 0) {
        float m1 = w1[0], m2 = w2[0];
        #pragma unroll
        for (int q = 1; q < 8; q++) { m1 = fmaxf(m1, w1[q]); m2 = fmaxf(m2, w2[q]); }
        g_red[b] = m1 + m2;
    }
}
__global__ void loss2_kernel(float* __restrict__ out)
{
    __shared__ float sm[BATCH];
    int t = threadIdx.x;
    sm[t] = g_red[t];
    __syncthreads();
    #pragma unroll
    for (int o = 128; o > 0; o >>= 1) {
        if (t < o) sm[t] += sm[t + o];
        __syncthreads();
    }
    if (t == 0) out[0] = sm[0];
}

// ============================================================================
extern "C" void kernel_launch(void* const* d_in, const int* in_sizes, int n_in,
                              void* d_out, int out_size)
{
    const float* im_set = (const float*)d_in[0];
    const float* s_seq  = (const float*)d_in[1];
    const int*   im_len = (const int*)d_in[2];
    const int*   s_len  = (const int*)d_in[3];
    float* out = (float*)d_out;

    cudaFuncSetAttribute(gemm_kernel, cudaFuncAttributeMaxDynamicSharedMemorySize,
                         STAGES * STAGE_BYTES);

    norm_kernel<<<BATCH * LI, 256>>>(im_set, L_IM, LI, 0);
    norm_kernel<<<BATCH * LS, 256>>>(s_seq,  L_S,  LS, 1);

    dim3 grid(NCOLS / BN, MROWS / BM);   // (60, 64)
    gemm_kernel<<<grid, NTH, STAGES * STAGE_BYTES>>>(im_len);

    score_kernel<<<BATCH * BATCH / 8, 256>>>(s_len);

    loss1_kernel<<<BATCH, 256>>>();
    loss2_kernel<<<1, BATCH>>>(out);
}

// round 8
// speedup vs baseline: 1.1462x; 1.0231x over previous
#include <cuda_runtime.h>
#include <cuda_fp16.h>
#include <math.h>
#include <stdint.h>

// Problem constants
#define BATCH 256
#define DIM   1024
#define L_IM  37
#define L_S   33
#define LI    36
#define LS    30
#define MARGIN 0.2f

#define MROWS  (BATCH*LI)     // 9216
#define NCOLS  (BATCH*LS)     // 7680

// ---- device scratch (allocation-free rule) ----
__device__ __half g_A[(size_t)MROWS * DIM];          // fp16 normalized images   18.9 MB
__device__ __half g_B[(size_t)NCOLS * DIM];          // fp16 normalized words    15.7 MB
__device__ float  g_colmax[(size_t)BATCH * NCOLS];   // masked max over regions  7.9 MB
__device__ float  g_scores[BATCH * BATCH];
__device__ float  g_red[BATCH];

__device__ __forceinline__ uint32_t s2u(const void* p) {
    return (uint32_t)__cvta_generic_to_shared(p);
}

// ============================================================================
// Kernel 1: L2-normalize + slice + fp16 convert. One block per output row.
// ============================================================================
__global__ void norm_kernel(const float* __restrict__ in, int Lin, int Lout, int which)
{
    int ob = blockIdx.x;
    int b  = ob / Lout;
    int i  = ob % Lout;
    const float4* src = (const float4*)(in + ((size_t)b * Lin + i + 1) * DIM);
    float4 v = src[threadIdx.x];

    float ss = v.x*v.x + v.y*v.y + v.z*v.z + v.w*v.w;
    #pragma unroll
    for (int o = 16; o > 0; o >>= 1) ss += __shfl_down_sync(0xffffffffu, ss, o);

    __shared__ float warp_s[8];
    __shared__ float inv_s;
    if ((threadIdx.x & 31) == 0) warp_s[threadIdx.x >> 5] = ss;
    __syncthreads();
    if (threadIdx.x == 0) {
        float tot = 0.f;
        #pragma unroll
        for (int q = 0; q < 8; q++) tot += warp_s[q];
        inv_s = 1.0f / fmaxf(sqrtf(tot), 1e-12f);
    }
    __syncthreads();
    float inv = inv_s;

    __half2 h01 = __floats2half2_rn(v.x * inv, v.y * inv);
    __half2 h23 = __floats2half2_rn(v.z * inv, v.w * inv);
    __half* dst = (which ? g_B : g_A) + (size_t)ob * DIM + 4 * threadIdx.x;
    *(__half2*)(dst)     = h01;
    *(__half2*)(dst + 2) = h23;
}

// ============================================================================
// Kernel 2: fp16 mma.sync GEMM with FUSED masked max-over-regions epilogue.
//   CTA 144x128x32 (144 rows = exactly 4 images), 192 threads, occ 2,
//   6 warps of 48x64 (3 m-groups x 2 n-groups), 5-stage cp.async pipeline.
//   A and B fragments both via ldmatrix.x4.
// ============================================================================
#define BM 144
#define BN 128
#define BKH 32                      // K halfs per stage
#define STAGES 5
#define ROWB 80                     // padded smem row bytes (32 halfs + 8 pad)
#define STAGE_BYTES ((BM + BN) * ROWB)   // 21760
#define KTILES (DIM / BKH)          // 32
#define NTH 192
#define ESTR 132                    // epilogue fp32 tile row stride (floats)

__device__ __forceinline__ void cp16(uint32_t dst, const void* src) {
    asm volatile("cp.async.cg.shared.global [%0], [%1], 16;" :: "r"(dst), "l"(src));
}

__device__ __forceinline__ void load_stage(char* dsm, int slot, int m0, int n0, int kc, int t)
{
    char* As = dsm + slot * STAGE_BYTES;
    char* Bs = As + BM * ROWB;
    const __half* Agp = g_A + (size_t)m0 * DIM + kc * BKH;
    const __half* Bgp = g_B + (size_t)n0 * DIM + kc * BKH;
    #pragma unroll
    for (int i = 0; i < 3; i++) {                 // 576 = 3 * 192 A-vectors
        int idx = t + i * NTH;
        int row = idx >> 2, seg = idx & 3;
        cp16(s2u(As + row * ROWB + seg * 16), Agp + (size_t)row * DIM + seg * 8);
    }
    #pragma unroll
    for (int i = 0; i < 3; i++) {                 // 512 B-vectors (last iter partial)
        int idx = t + i * NTH;
        if (idx < 512) {
            int row = idx >> 2, seg = idx & 3;
            cp16(s2u(Bs + row * ROWB + seg * 16), Bgp + (size_t)row * DIM + seg * 8);
        }
    }
}

__global__ __launch_bounds__(NTH, 2) void gemm_kernel(const int* __restrict__ im_len)
{
    extern __shared__ __align__(128) char dsm[];
    const int t   = threadIdx.x;
    const int wid = t >> 5, lid = t & 31;
    const int warp_m = (wid % 3) * 48;
    const int warp_n = (wid / 3) * 64;
    const int m0 = blockIdx.y * BM;
    const int n0 = blockIdx.x * BN;

    float acc[3][8][4];
    #pragma unroll
    for (int mf = 0; mf < 3; mf++)
        #pragma unroll
        for (int nf = 0; nf < 8; nf++)
            #pragma unroll
            for (int q = 0; q < 4; q++) acc[mf][nf][q] = 0.f;

    #pragma unroll
    for (int s = 0; s < STAGES - 1; s++) {        // fill stages 0..3
        load_stage(dsm, s, m0, n0, s, t);
        asm volatile("cp.async.commit_group;");
    }

    // B ldmatrix lane address components (validated):
    const int b_nrow = ((lid >> 4) & 1) * 8 + (lid & 7);   // n row within 16-block
    const int b_koff = ((lid >> 3) & 1) * 16;              // byte offset for k-half

    for (int j = 0; j < KTILES; j++) {
        if (j < KTILES - 3)       asm volatile("cp.async.wait_group 3;");
        else if (j == KTILES - 3) asm volatile("cp.async.wait_group 2;");
        else if (j == KTILES - 2) asm volatile("cp.async.wait_group 1;");
        else                      asm volatile("cp.async.wait_group 0;");
        __syncthreads();

        int jl = j + STAGES - 1;
        if (jl < KTILES) {
            load_stage(dsm, jl % STAGES, m0, n0, jl, t);
            asm volatile("cp.async.commit_group;");
        }

        char* As = dsm + (j % STAGES) * STAGE_BYTES;
        const uint32_t AsU = s2u(As);
        const uint32_t BsU = AsU + BM * ROWB;

        #pragma unroll
        for (int ks = 0; ks < 2; ks++) {
            uint32_t a[3][4];
            #pragma unroll
            for (int mf = 0; mf < 3; mf++) {
                uint32_t addr = AsU + (warp_m + mf * 16 + (lid & 15)) * ROWB
                                    + ((lid >> 4) * 8 + ks * 16) * 2;
                asm volatile("ldmatrix.sync.aligned.m8n8.x4.shared.b16 {%0,%1,%2,%3}, [%4];"
                    : "=r"(a[mf][0]), "=r"(a[mf][1]), "=r"(a[mf][2]), "=r"(a[mf][3])
                    : "r"(addr));
            }
            uint32_t bf[4][4];        // [np: 16-n block][nf-even b0,b1, nf-odd b0,b1]
            #pragma unroll
            for (int np = 0; np < 4; np++) {
                uint32_t addr = BsU + (warp_n + np * 16 + b_nrow) * ROWB
                                    + ks * 32 + b_koff;
                asm volatile("ldmatrix.sync.aligned.m8n8.x4.shared.b16 {%0,%1,%2,%3}, [%4];"
                    : "=r"(bf[np][0]), "=r"(bf[np][1]), "=r"(bf[np][2]), "=r"(bf[np][3])
                    : "r"(addr));
            }
            #pragma unroll
            for (int nf = 0; nf < 8; nf++) {
                uint32_t b0 = bf[nf >> 1][(nf & 1) * 2];
                uint32_t b1 = bf[nf >> 1][(nf & 1) * 2 + 1];
                #pragma unroll
                for (int mf = 0; mf < 3; mf++) {
                    asm volatile(
                        "mma.sync.aligned.m16n8k16.row.col.f32.f16.f16.f32 "
                        "{%0,%1,%2,%3}, {%4,%5,%6,%7}, {%8,%9}, {%0,%1,%2,%3};"
                        : "+f"(acc[mf][nf][0]), "+f"(acc[mf][nf][1]),
                          "+f"(acc[mf][nf][2]), "+f"(acc[mf][nf][3])
                        : "r"(a[mf][0]), "r"(a[mf][1]), "r"(a[mf][2]), "r"(a[mf][3]),
                          "r"(b0), "r"(b1));
                }
            }
        }
    }

    // ---- fused epilogue: accs -> smem fp32 tile [144][128] (stride ESTR) ----
    __syncthreads();
    float* etile = (float*)dsm;            // 144*132*4 = 76032 B (< stage smem)
    const int r0 = warp_m + (lid >> 2);
    const int c0 = warp_n + (lid & 3) * 2;
    #pragma unroll
    for (int mf = 0; mf < 3; mf++) {
        #pragma unroll
        for (int nf = 0; nf < 8; nf++) {
            int r = r0 + mf * 16;
            int c = c0 + nf * 8;
            etile[r * ESTR + c]           = acc[mf][nf][0];
            etile[r * ESTR + c + 1]       = acc[mf][nf][1];
            etile[(r + 8) * ESTR + c]     = acc[mf][nf][2];
            etile[(r + 8) * ESTR + c + 1] = acc[mf][nf][3];
        }
    }
    __syncthreads();

    // masked column max per (image, col): 4 images x 128 cols = 512 outputs
    const int bimg0 = blockIdx.y * 4;
    for (int idx = t; idx < 512; idx += NTH) {
        int img = idx >> 7, col = idx & 127;
        int iml = im_len[bimg0 + img] - 1;           // valid rows (9..36)
        const float* colp = etile + img * 36 * ESTR + col;
        float m = -1e30f;
        for (int r = 0; r < iml; r++) m = fmaxf(m, colp[r * ESTR]);
        if (iml < LI) m = fmaxf(m, 0.f);             // reference zeros padded rows
        g_colmax[(size_t)(bimg0 + img) * NCOLS + n0 + col] = m;
    }
}

// ============================================================================
// Kernel 3: scores[b][c] = sum_{j < sl} colmax[b][c*30+j].
//   Block per image b: coalesced row staging in smem, thread per sentence.
// ============================================================================
__global__ __launch_bounds__(256) void score_kernel(const int* __restrict__ s_len)
{
    __shared__ float row[NCOLS];           // 30720 B
    const int b = blockIdx.x, t = threadIdx.x;
    const float4* src = (const float4*)(g_colmax + (size_t)b * NCOLS);
    #pragma unroll
    for (int i = 0; i < 8; i++) {          // ceil(1920 / 256) = 8, guard last
        int idx = t + i * 256;
        if (idx < NCOLS / 4)
            *(float4*)(row + 4 * idx) = src[idx];
    }
    __syncthreads();

    int sl = s_len[t] - 3;
    if (sl > LS) sl = LS;
    if (sl < 0)  sl = 0;
    const float* p = row + t * LS;
    float sum = 0.f;
    for (int j = 0; j < sl; j++) sum += p[j];
    g_scores[b * BATCH + t] = sum;
}

// ============================================================================
// Kernel 4/5: contrastive loss
// ============================================================================
__global__ void loss1_kernel()
{
    int b = blockIdx.x, t = threadIdx.x;
    __shared__ float sd;
    __shared__ float w1[8], w2[8];
    if (t == 0) sd = g_scores[b * BATCH + b];
    __syncthreads();
    float d = sd;
    float v1 = 0.f, v2 = 0.f;
    if (t != b) {
        v1 = fmaxf(0.f, MARGIN + g_scores[b * BATCH + t] - d);
        v2 = fmaxf(0.f, MARGIN + g_scores[t * BATCH + b] - d);
    }
    #pragma unroll
    for (int o = 16; o > 0; o >>= 1) {
        v1 = fmaxf(v1, __shfl_down_sync(0xffffffffu, v1, o));
        v2 = fmaxf(v2, __shfl_down_sync(0xffffffffu, v2, o));
    }
    if ((t & 31) == 0) { w1[t >> 5] = v1; w2[t >> 5] = v2; }
    __syncthreads();
    if (t == 0) {
        float m1 = w1[0], m2 = w2[0];
        #pragma unroll
        for (int q = 1; q < 8; q++) { m1 = fmaxf(m1, w1[q]); m2 = fmaxf(m2, w2[q]); }
        g_red[b] = m1 + m2;
    }
}
__global__ void loss2_kernel(float* __restrict__ out)
{
    __shared__ float sm[BATCH];
    int t = threadIdx.x;
    sm[t] = g_red[t];
    __syncthreads();
    #pragma unroll
    for (int o = 128; o > 0; o >>= 1) {
        if (t < o) sm[t] += sm[t + o];
        __syncthreads();
    }
    if (t == 0) out[0] = sm[0];
}

// ============================================================================
extern "C" void kernel_launch(void* const* d_in, const int* in_sizes, int n_in,
                              void* d_out, int out_size)
{
    const float* im_set = (const float*)d_in[0];
    const float* s_seq  = (const float*)d_in[1];
    const int*   im_len = (const int*)d_in[2];
    const int*   s_len  = (const int*)d_in[3];
    float* out = (float*)d_out;

    cudaFuncSetAttribute(gemm_kernel, cudaFuncAttributeMaxDynamicSharedMemorySize,
                         STAGES * STAGE_BYTES);

    norm_kernel<<<BATCH * LI, 256>>>(im_set, L_IM, LI, 0);
    norm_kernel<<<BATCH * LS, 256>>>(s_seq,  L_S,  LS, 1);

    dim3 grid(NCOLS / BN, MROWS / BM);   // (60, 64)
    gemm_kernel<<<grid, NTH, STAGES * STAGE_BYTES>>>(im_len);

    score_kernel<<<BATCH, 256>>>(s_len);

    loss1_kernel<<<BATCH, 256>>>();
    loss2_kernel<<<1, BATCH>>>(out);
}

// round 9
// speedup vs baseline: 1.3493x; 1.1772x over previous
#include <cuda_runtime.h>
#include <cuda_fp16.h>
#include <math.h>
#include <stdint.h>

// Problem constants
#define BATCH 256
#define DIM   1024
#define L_IM  37
#define L_S   33
#define LI    36
#define LS    30
#define MARGIN 0.2f

#define MROWS  (BATCH*LI)     // 9216
#define NCOLS  (BATCH*LS)     // 7680

// ---- device scratch (allocation-free rule) ----
__device__ __half g_A[(size_t)MROWS * DIM];          // fp16 normalized images   18.9 MB
__device__ __half g_B[(size_t)NCOLS * DIM];          // fp16 normalized words    15.7 MB
__device__ float  g_colmax[(size_t)BATCH * NCOLS];   // masked max over regions  7.9 MB
__device__ float  g_scores[BATCH * BATCH];
__device__ float  g_red[BATCH];

__device__ __forceinline__ uint32_t s2u(const void* p) {
    return (uint32_t)__cvta_generic_to_shared(p);
}

// ============================================================================
// Kernel 1: L2-normalize + slice + fp16 convert (both tensors, one launch).
//   Blocks [0, 9216): image rows -> g_A ; [9216, 16896): sentence -> g_B.
// ============================================================================
__global__ void norm_kernel(const float* __restrict__ im_in, const float* __restrict__ s_in)
{
    int ob = blockIdx.x;
    int which = (ob >= MROWS);
    const float* in = which ? s_in : im_in;
    int Lin  = which ? L_S : L_IM;
    int Lout = which ? LS  : LI;
    if (which) ob -= MROWS;
    int b = ob / Lout;
    int i = ob % Lout;
    const float4* src = (const float4*)(in + ((size_t)b * Lin + i + 1) * DIM);
    float4 v = src[threadIdx.x];

    float ss = v.x*v.x + v.y*v.y + v.z*v.z + v.w*v.w;
    #pragma unroll
    for (int o = 16; o > 0; o >>= 1) ss += __shfl_down_sync(0xffffffffu, ss, o);

    __shared__ float warp_s[8];
    __shared__ float inv_s;
    if ((threadIdx.x & 31) == 0) warp_s[threadIdx.x >> 5] = ss;
    __syncthreads();
    if (threadIdx.x == 0) {
        float tot = 0.f;
        #pragma unroll
        for (int q = 0; q < 8; q++) tot += warp_s[q];
        inv_s = 1.0f / fmaxf(sqrtf(tot), 1e-12f);
    }
    __syncthreads();
    float inv = inv_s;

    __half2 h01 = __floats2half2_rn(v.x * inv, v.y * inv);
    __half2 h23 = __floats2half2_rn(v.z * inv, v.w * inv);
    __half* dst = (which ? g_B : g_A) + (size_t)ob * DIM + 4 * threadIdx.x;
    *(__half2*)(dst)     = h01;
    *(__half2*)(dst + 2) = h23;
}

// ============================================================================
// Kernel 2: fp16 mma.sync GEMM with FUSED masked max-over-regions epilogue.
//   CTA 144x128x32 (144 rows = 4 images), 192 threads, occ 2,
//   6 warps of 48x64, 6-stage cp.async pipeline,
//   compact 64B smem rows with XOR swizzle (seg ^= (row>>1)&3).
// ============================================================================
#define BM 144
#define BN 128
#define BKH 32                      // K halfs per stage
#define STAGES 6
#define ROWB 64                     // compact row: 32 halfs = 64 bytes
#define STAGE_BYTES ((BM + BN) * ROWB)   // 17408
#define KTILES (DIM / BKH)          // 32
#define NTH 192
#define ESTR 132                    // epilogue fp32 tile row stride (floats)
#define SMEM_SZ (STAGES * STAGE_BYTES)   // 104448 (> 144*132*4 = 76032)

__device__ __forceinline__ void cp16(uint32_t dst, const void* src) {
    asm volatile("cp.async.cg.shared.global [%0], [%1], 16;" :: "r"(dst), "l"(src));
}

// swizzled byte offset of 16B segment `seg` (0..3) in row `row`
__device__ __forceinline__ uint32_t swz(int row, int seg) {
    return (uint32_t)(row * ROWB + ((seg ^ ((row >> 1) & 3)) << 4));
}

__device__ __forceinline__ void load_stage(char* dsm, int slot, int m0, int n0, int kc, int t)
{
    char* As = dsm + slot * STAGE_BYTES;
    char* Bs = As + BM * ROWB;
    const __half* Agp = g_A + (size_t)m0 * DIM + kc * BKH;
    const __half* Bgp = g_B + (size_t)n0 * DIM + kc * BKH;
    #pragma unroll
    for (int i = 0; i < 3; i++) {                 // 576 = 3 * 192 A-vectors
        int idx = t + i * NTH;
        int row = idx >> 2, seg = idx & 3;
        cp16(s2u(As + swz(row, seg)), Agp + (size_t)row * DIM + seg * 8);
    }
    #pragma unroll
    for (int i = 0; i < 3; i++) {                 // 512 B-vectors (last iter partial)
        int idx = t + i * NTH;
        if (idx < 512) {
            int row = idx >> 2, seg = idx & 3;
            cp16(s2u(Bs + swz(row, seg)), Bgp + (size_t)row * DIM + seg * 8);
        }
    }
}

__global__ __launch_bounds__(NTH, 2) void gemm_kernel(const int* __restrict__ im_len)
{
    extern __shared__ __align__(128) char dsm[];
    const int t   = threadIdx.x;
    const int wid = t >> 5, lid = t & 31;
    const int warp_m = (wid % 3) * 48;
    const int warp_n = (wid / 3) * 64;
    const int m0 = blockIdx.y * BM;
    const int n0 = blockIdx.x * BN;

    float acc[3][8][4];
    #pragma unroll
    for (int mf = 0; mf < 3; mf++)
        #pragma unroll
        for (int nf = 0; nf < 8; nf++)
            #pragma unroll
            for (int q = 0; q < 4; q++) acc[mf][nf][q] = 0.f;

    #pragma unroll
    for (int s = 0; s < STAGES - 1; s++) {        // fill stages 0..4
        load_stage(dsm, s, m0, n0, s, t);
        asm volatile("cp.async.commit_group;");
    }

    // k-invariant fragment addressing (precomputed per lane)
    int rowA[3], swzA[3];
    #pragma unroll
    for (int mf = 0; mf < 3; mf++) {
        rowA[mf] = warp_m + mf * 16 + (lid & 15);
        swzA[mf] = (rowA[mf] >> 1) & 3;
    }
    const int a_seg0 = (lid >> 4);                       // + 2*ks
    const int b_row_base = warp_n + ((lid >> 4) & 1) * 8 + (lid & 7);
    const int b_seg0 = (lid >> 3) & 1;                   // + 2*ks

    int slot = 0, lslot = STAGES - 1;
    for (int j = 0; j < KTILES; j++) {
        if (j < KTILES - 4)       asm volatile("cp.async.wait_group 4;");
        else if (j == KTILES - 4) asm volatile("cp.async.wait_group 3;");
        else if (j == KTILES - 3) asm volatile("cp.async.wait_group 2;");
        else if (j == KTILES - 2) asm volatile("cp.async.wait_group 1;");
        else                      asm volatile("cp.async.wait_group 0;");
        __syncthreads();

        int jl = j + STAGES - 1;
        if (jl < KTILES) {
            load_stage(dsm, lslot, m0, n0, jl, t);
            asm volatile("cp.async.commit_group;");
        }

        const uint32_t AsU = s2u(dsm) + slot * STAGE_BYTES;
        const uint32_t BsU = AsU + BM * ROWB;

        #pragma unroll
        for (int ks = 0; ks < 2; ks++) {
            uint32_t a[3][4];
            #pragma unroll
            for (int mf = 0; mf < 3; mf++) {
                uint32_t addr = AsU + rowA[mf] * ROWB
                              + (((a_seg0 + 2 * ks) ^ swzA[mf]) << 4);
                asm volatile("ldmatrix.sync.aligned.m8n8.x4.shared.b16 {%0,%1,%2,%3}, [%4];"
                    : "=r"(a[mf][0]), "=r"(a[mf][1]), "=r"(a[mf][2]), "=r"(a[mf][3])
                    : "r"(addr));
            }
            uint32_t bf[4][4];        // [np: 16-n block][nf-even b0,b1, nf-odd b0,b1]
            #pragma unroll
            for (int np = 0; np < 4; np++) {
                int row = b_row_base + np * 16;
                uint32_t addr = BsU + row * ROWB
                              + (((b_seg0 + 2 * ks) ^ ((row >> 1) & 3)) << 4);
                asm volatile("ldmatrix.sync.aligned.m8n8.x4.shared.b16 {%0,%1,%2,%3}, [%4];"
                    : "=r"(bf[np][0]), "=r"(bf[np][1]), "=r"(bf[np][2]), "=r"(bf[np][3])
                    : "r"(addr));
            }
            #pragma unroll
            for (int nf = 0; nf < 8; nf++) {
                uint32_t b0 = bf[nf >> 1][(nf & 1) * 2];
                uint32_t b1 = bf[nf >> 1][(nf & 1) * 2 + 1];
                #pragma unroll
                for (int mf = 0; mf < 3; mf++) {
                    asm volatile(
                        "mma.sync.aligned.m16n8k16.row.col.f32.f16.f16.f32 "
                        "{%0,%1,%2,%3}, {%4,%5,%6,%7}, {%8,%9}, {%0,%1,%2,%3};"
                        : "+f"(acc[mf][nf][0]), "+f"(acc[mf][nf][1]),
                          "+f"(acc[mf][nf][2]), "+f"(acc[mf][nf][3])
                        : "r"(a[mf][0]), "r"(a[mf][1]), "r"(a[mf][2]), "r"(a[mf][3]),
                          "r"(b0), "r"(b1));
                }
            }
        }
        slot  = (slot  == STAGES - 1) ? 0 : slot + 1;
        lslot = (lslot == STAGES - 1) ? 0 : lslot + 1;
    }

    // ---- fused epilogue: accs -> smem fp32 tile [144][128] (stride ESTR) ----
    __syncthreads();
    float* etile = (float*)dsm;            // 76032 B < SMEM_SZ
    const int r0 = warp_m + (lid >> 2);
    const int c0 = warp_n + (lid & 3) * 2;
    #pragma unroll
    for (int mf = 0; mf < 3; mf++) {
        #pragma unroll
        for (int nf = 0; nf < 8; nf++) {
            int r = r0 + mf * 16;
            int c = c0 + nf * 8;
            etile[r * ESTR + c]           = acc[mf][nf][0];
            etile[r * ESTR + c + 1]       = acc[mf][nf][1];
            etile[(r + 8) * ESTR + c]     = acc[mf][nf][2];
            etile[(r + 8) * ESTR + c + 1] = acc[mf][nf][3];
        }
    }
    __syncthreads();

    // masked column max per (image, col): 4 images x 128 cols = 512 outputs
    const int bimg0 = blockIdx.y * 4;
    for (int idx = t; idx < 512; idx += NTH) {
        int img = idx >> 7, col = idx & 127;
        int iml = im_len[bimg0 + img] - 1;           // valid rows (9..36)
        const float* colp = etile + img * 36 * ESTR + col;
        float m = -1e30f;
        for (int r = 0; r < iml; r++) m = fmaxf(m, colp[r * ESTR]);
        if (iml < LI) m = fmaxf(m, 0.f);             // reference zeros padded rows
        g_colmax[(size_t)(bimg0 + img) * NCOLS + n0 + col] = m;
    }
}

// ============================================================================
// Kernel 3: scores[b][c] = sum_{j < sl} colmax[b][c*30+j].
// ============================================================================
__global__ __launch_bounds__(256) void score_kernel(const int* __restrict__ s_len)
{
    __shared__ float row[NCOLS];           // 30720 B
    const int b = blockIdx.x, t = threadIdx.x;
    const float4* src = (const float4*)(g_colmax + (size_t)b * NCOLS);
    #pragma unroll
    for (int i = 0; i < 8; i++) {
        int idx = t + i * 256;
        if (idx < NCOLS / 4)
            *(float4*)(row + 4 * idx) = src[idx];
    }
    __syncthreads();

    int sl = s_len[t] - 3;
    if (sl > LS) sl = LS;
    if (sl < 0)  sl = 0;
    const float* p = row + t * LS;
    float sum = 0.f;
    for (int j = 0; j < sl; j++) sum += p[j];
    g_scores[b * BATCH + t] = sum;
}

// ============================================================================
// Kernel 4/5: contrastive loss
// ============================================================================
__global__ void loss1_kernel()
{
    int b = blockIdx.x, t = threadIdx.x;
    __shared__ float sd;
    __shared__ float w1[8], w2[8];
    if (t == 0) sd = g_scores[b * BATCH + b];
    __syncthreads();
    float d = sd;
    float v1 = 0.f, v2 = 0.f;
    if (t != b) {
        v1 = fmaxf(0.f, MARGIN + g_scores[b * BATCH + t] - d);
        v2 = fmaxf(0.f, MARGIN + g_scores[t * BATCH + b] - d);
    }
    #pragma unroll
    for (int o = 16; o > 0; o >>= 1) {
        v1 = fmaxf(v1, __shfl_down_sync(0xffffffffu, v1, o));
        v2 = fmaxf(v2, __shfl_down_sync(0xffffffffu, v2, o));
    }
    if ((t & 31) == 0) { w1[t >> 5] = v1; w2[t >> 5] = v2; }
    __syncthreads();
    if (t == 0) {
        float m1 = w1[0], m2 = w2[0];
        #pragma unroll
        for (int q = 1; q < 8; q++) { m1 = fmaxf(m1, w1[q]); m2 = fmaxf(m2, w2[q]); }
        g_red[b] = m1 + m2;
    }
}
__global__ void loss2_kernel(float* __restrict__ out)
{
    __shared__ float sm[BATCH];
    int t = threadIdx.x;
    sm[t] = g_red[t];
    __syncthreads();
    #pragma unroll
    for (int o = 128; o > 0; o >>= 1) {
        if (t < o) sm[t] += sm[t + o];
        __syncthreads();
    }
    if (t == 0) out[0] = sm[0];
}

// ============================================================================
extern "C" void kernel_launch(void* const* d_in, const int* in_sizes, int n_in,
                              void* d_out, int out_size)
{
    const float* im_set = (const float*)d_in[0];
    const float* s_seq  = (const float*)d_in[1];
    const int*   im_len = (const int*)d_in[2];
    const int*   s_len  = (const int*)d_in[3];
    float* out = (float*)d_out;

    cudaFuncSetAttribute(gemm_kernel, cudaFuncAttributeMaxDynamicSharedMemorySize,
                         SMEM_SZ);

    norm_kernel<<<BATCH * LI + BATCH * LS, 256>>>(im_set, s_seq);

    dim3 grid(NCOLS / BN, MROWS / BM);   // (60, 64)
    gemm_kernel<<<grid, NTH, SMEM_SZ>>>(im_len);

    score_kernel<<<BATCH, 256>>>(s_len);

    loss1_kernel<<<BATCH, 256>>>();
    loss2_kernel<<<1, BATCH>>>(out);
}